// round 1
// baseline (speedup 1.0000x reference)
#include <cuda_runtime.h>
#include <math.h>

#define HID 64
#define SEQL 200
#define NBATCH 128
#define TOK (NBATCH * SEQL)   // 25600
#define NBLOCKS 2

// ---------------- scratch (device globals; no allocation) ----------------
__device__ float g_seqs[TOK * HID];
__device__ float g_Q[TOK * HID];
__device__ float g_q[TOK * HID];
__device__ float g_k[TOK * HID];
__device__ float g_v[TOK * HID];
__device__ float g_ctx[TOK * HID];
__device__ float g_h[TOK * HID];

// ---------------- embed: seqs = (A[idx]@B + item_emb[idx]) * 8 + pos_emb ----------------
__global__ void embed_kernel(const int* __restrict__ log_seqs,
                             const float* __restrict__ item_emb,
                             const float* __restrict__ pos_emb,
                             const float* __restrict__ A,
                             const float* __restrict__ Bm) {
    int w = (blockIdx.x * blockDim.x + threadIdx.x) >> 5;
    int lane = threadIdx.x & 31;
    if (w >= TOK) return;
    int l = w % SEQL;
    int idx = log_seqs[w];
    float a = (lane < 8) ? A[idx * 8 + lane] : 0.0f;
    int d0 = lane * 2, d1 = d0 + 1;
    float e0 = item_emb[idx * 64 + d0];
    float e1 = item_emb[idx * 64 + d1];
#pragma unroll
    for (int r = 0; r < 8; r++) {
        float ar = __shfl_sync(0xffffffffu, a, r);
        e0 += ar * Bm[r * 64 + d0];
        e1 += ar * Bm[r * 64 + d1];
    }
    int pos = (idx != 0) ? (l + 1) : 0;
    g_seqs[w * 64 + d0] = e0 * 8.0f + pos_emb[pos * 64 + d0];
    g_seqs[w * 64 + d1] = e1 * 8.0f + pos_emb[pos * 64 + d1];
}

// ---------------- layernorm over last dim (64), warp per token ----------------
__global__ void ln_kernel(const float* __restrict__ in, float* __restrict__ out,
                          const float* __restrict__ g, const float* __restrict__ b) {
    int w = (blockIdx.x * blockDim.x + threadIdx.x) >> 5;
    int lane = threadIdx.x & 31;
    if (w >= TOK) return;
    int d0 = lane * 2, d1 = d0 + 1;
    float x0 = in[w * 64 + d0], x1 = in[w * 64 + d1];
    float s = x0 + x1;
#pragma unroll
    for (int o = 16; o; o >>= 1) s += __shfl_xor_sync(0xffffffffu, s, o);
    float mu = s * (1.0f / 64.0f);
    float dx0 = x0 - mu, dx1 = x1 - mu;
    float v = dx0 * dx0 + dx1 * dx1;
#pragma unroll
    for (int o = 16; o; o >>= 1) v += __shfl_xor_sync(0xffffffffu, v, o);
    float inv = rsqrtf(v * (1.0f / 64.0f) + 1e-8f);
    out[w * 64 + d0] = dx0 * inv * g[d0] + b[d0];
    out[w * 64 + d1] = dx1 * inv * g[d1] + b[d1];
}

// ---------------- Y[t][c] = op( X[t][:] @ W[c][:] + bias[c] (+ res) ) ----------------
// W is row-major [64(out)][64(in)]. Tile: 64 tokens per CTA, 256 threads, 4x4 per thread.
template <bool RELU, bool RES>
__global__ void gemm64_kernel(const float* __restrict__ X, const float* __restrict__ W,
                              const float* __restrict__ bias, const float* __restrict__ res,
                              float* __restrict__ Y) {
    __shared__ float Xs[64][65];
    __shared__ float Wt[64][65];   // Wt[k][c] = W[c][k]
    int t0 = blockIdx.x * 64;
    int tid = threadIdx.x;
    for (int i = tid; i < 4096; i += 256) {
        int r = i >> 6, c = i & 63;
        Xs[r][c] = X[(t0 + r) * 64 + c];
        Wt[c][r] = W[i];
    }
    __syncthreads();
    int tc = tid & 15, tr = tid >> 4;
    int c0 = tc * 4, r0 = tr * 4;
    float acc[4][4];
#pragma unroll
    for (int i = 0; i < 4; i++)
#pragma unroll
        for (int j = 0; j < 4; j++) acc[i][j] = bias[c0 + j];
#pragma unroll 8
    for (int k = 0; k < 64; k++) {
        float xv[4], wv[4];
#pragma unroll
        for (int i = 0; i < 4; i++) xv[i] = Xs[r0 + i][k];
#pragma unroll
        for (int j = 0; j < 4; j++) wv[j] = Wt[k][c0 + j];
#pragma unroll
        for (int i = 0; i < 4; i++)
#pragma unroll
            for (int j = 0; j < 4; j++) acc[i][j] += xv[i] * wv[j];
    }
#pragma unroll
    for (int i = 0; i < 4; i++) {
        int row = t0 + r0 + i;
        float4 o;
        o.x = acc[i][0]; o.y = acc[i][1]; o.z = acc[i][2]; o.w = acc[i][3];
        if (RELU) {
            o.x = fmaxf(o.x, 0.f); o.y = fmaxf(o.y, 0.f);
            o.z = fmaxf(o.z, 0.f); o.w = fmaxf(o.w, 0.f);
        }
        if (RES) {
            float4 rr = *reinterpret_cast<const float4*>(&res[row * 64 + c0]);
            o.x += rr.x; o.y += rr.y; o.z += rr.z; o.w += rr.w;
        }
        *reinterpret_cast<float4*>(&Y[row * 64 + c0]) = o;
    }
}

// ---------------- causal attention, 1 head, hd=64: one CTA per batch ----------------
// smem: ks[200][65], vs[200][64], sc[8][200], qs[8][64]
__global__ void attn_kernel() {
    extern __shared__ float sm[];
    float* ks = sm;                        // 200*65
    float* vs = ks + SEQL * 65;            // 200*64
    float* sc = vs + SEQL * 64;            // 8*200
    float* qs = sc + 8 * SEQL;             // 8*64
    int b = blockIdx.x;
    int tid = threadIdx.x, lane = tid & 31, w = tid >> 5;
    const float* kg = g_k + b * SEQL * 64;
    const float* vg = g_v + b * SEQL * 64;
    for (int i = tid; i < SEQL * 64; i += 256) {
        int j = i >> 6, d = i & 63;
        ks[j * 65 + d] = kg[i];
        vs[i] = vg[i];
    }
    __syncthreads();
    for (int q = w; q < SEQL; q += 8) {
        const float* qg = g_q + (b * SEQL + q) * 64;
        qs[w * 64 + lane * 2]     = qg[lane * 2];
        qs[w * 64 + lane * 2 + 1] = qg[lane * 2 + 1];
        __syncwarp();
        int nk = q + 1;
        float lm = -1e30f;
        for (int j0 = 0; j0 < nk; j0 += 32) {
            int j = j0 + lane;
            if (j < nk) {
                float acc = 0.0f;
#pragma unroll 16
                for (int d = 0; d < 64; d++) acc += qs[w * 64 + d] * ks[j * 65 + d];
                acc *= 0.125f;
                sc[w * SEQL + j] = acc;
                lm = fmaxf(lm, acc);
            }
        }
#pragma unroll
        for (int o = 16; o; o >>= 1) lm = fmaxf(lm, __shfl_xor_sync(0xffffffffu, lm, o));
        float le = 0.0f;
        for (int j0 = 0; j0 < nk; j0 += 32) {
            int j = j0 + lane;
            if (j < nk) {
                float p = expf(sc[w * SEQL + j] - lm);
                sc[w * SEQL + j] = p;
                le += p;
            }
        }
#pragma unroll
        for (int o = 16; o; o >>= 1) le += __shfl_xor_sync(0xffffffffu, le, o);
        float inv = 1.0f / le;
        __syncwarp();
        int d0 = lane * 2;
        float c0 = 0.0f, c1 = 0.0f;
        for (int j = 0; j < nk; j++) {
            float p = sc[w * SEQL + j];
            float2 vv = *reinterpret_cast<const float2*>(&vs[j * 64 + d0]);
            c0 += p * vv.x;
            c1 += p * vv.y;
        }
        float* og = g_ctx + (b * SEQL + q) * 64;
        og[d0]     = c0 * inv;
        og[d0 + 1] = c1 * inv;
        __syncwarp();
    }
}

// ---------------- final: pos/neg logits via gathered low-rank embeddings ----------------
__global__ void final_kernel(const int* __restrict__ pos_seqs, const int* __restrict__ neg_seqs,
                             const float* __restrict__ item_emb,
                             const float* __restrict__ A, const float* __restrict__ Bm,
                             float* __restrict__ out) {
    int w = (blockIdx.x * blockDim.x + threadIdx.x) >> 5;
    int lane = threadIdx.x & 31;
    if (w >= TOK) return;
    int d0 = lane * 2, d1 = d0 + 1;
    float f0 = g_seqs[w * 64 + d0];
    float f1 = g_seqs[w * 64 + d1];
#pragma unroll
    for (int s = 0; s < 2; s++) {
        int idx = (s ? neg_seqs : pos_seqs)[w];
        float a = (lane < 8) ? A[idx * 8 + lane] : 0.0f;
        float e0 = item_emb[idx * 64 + d0];
        float e1 = item_emb[idx * 64 + d1];
#pragma unroll
        for (int r = 0; r < 8; r++) {
            float ar = __shfl_sync(0xffffffffu, a, r);
            e0 += ar * Bm[r * 64 + d0];
            e1 += ar * Bm[r * 64 + d1];
        }
        float acc = f0 * e0 + f1 * e1;
#pragma unroll
        for (int o = 16; o; o >>= 1) acc += __shfl_xor_sync(0xffffffffu, acc, o);
        if (lane == 0) out[s * TOK + w] = acc;
    }
}

// ---------------- launch ----------------
extern "C" void kernel_launch(void* const* d_in, const int* in_sizes, int n_in,
                              void* d_out, int out_size) {
    const int*   log_seqs   = (const int*)d_in[1];
    const int*   pos_seqs   = (const int*)d_in[2];
    const int*   neg_seqs   = (const int*)d_in[3];
    const float* item_emb   = (const float*)d_in[4];
    const float* pos_emb    = (const float*)d_in[5];
    const float* A          = (const float*)d_in[6];
    const float* Bm         = (const float*)d_in[7];
    const float* attn_ln_g  = (const float*)d_in[8];
    const float* attn_ln_b  = (const float*)d_in[9];
    const float* in_proj_w  = (const float*)d_in[10];
    const float* in_proj_b  = (const float*)d_in[11];
    const float* out_proj_w = (const float*)d_in[12];
    const float* out_proj_b = (const float*)d_in[13];
    const float* fwd_ln_g   = (const float*)d_in[14];
    const float* fwd_ln_b   = (const float*)d_in[15];
    const float* conv1_w    = (const float*)d_in[16];
    const float* conv1_b    = (const float*)d_in[17];
    const float* conv2_w    = (const float*)d_in[18];
    const float* conv2_b    = (const float*)d_in[19];
    const float* last_ln_g  = (const float*)d_in[20];
    const float* last_ln_b  = (const float*)d_in[21];
    float* out = (float*)d_out;

    float *p_seqs, *p_Q, *p_q, *p_k, *p_v, *p_ctx, *p_h;
    cudaGetSymbolAddress((void**)&p_seqs, g_seqs);
    cudaGetSymbolAddress((void**)&p_Q, g_Q);
    cudaGetSymbolAddress((void**)&p_q, g_q);
    cudaGetSymbolAddress((void**)&p_k, g_k);
    cudaGetSymbolAddress((void**)&p_v, g_v);
    cudaGetSymbolAddress((void**)&p_ctx, g_ctx);
    cudaGetSymbolAddress((void**)&p_h, g_h);

    const int WARP_BLOCKS = (TOK * 32) / 256;  // 3200 CTAs, warp per token
    const int GEMM_BLOCKS = TOK / 64;          // 400 CTAs

    size_t attn_smem = (size_t)(SEQL * 65 + SEQL * 64 + 8 * SEQL + 8 * 64) * sizeof(float);
    cudaFuncSetAttribute(attn_kernel, cudaFuncAttributeMaxDynamicSharedMemorySize, (int)attn_smem);

    embed_kernel<<<WARP_BLOCKS, 256>>>(log_seqs, item_emb, pos_emb, A, Bm);

    for (int i = 0; i < NBLOCKS; i++) {
        const float* wq = in_proj_w + (size_t)i * 192 * 64;
        const float* wk = wq + 64 * 64;
        const float* wv = wq + 128 * 64;
        const float* bq = in_proj_b + (size_t)i * 192;
        const float* bk = bq + 64;
        const float* bv = bq + 128;

        ln_kernel<<<WARP_BLOCKS, 256>>>(p_seqs, p_Q, attn_ln_g + i * 64, attn_ln_b + i * 64);
        gemm64_kernel<false, false><<<GEMM_BLOCKS, 256>>>(p_Q, wq, bq, nullptr, p_q);
        gemm64_kernel<false, false><<<GEMM_BLOCKS, 256>>>(p_seqs, wk, bk, nullptr, p_k);
        gemm64_kernel<false, false><<<GEMM_BLOCKS, 256>>>(p_seqs, wv, bv, nullptr, p_v);
        attn_kernel<<<NBATCH, 256, attn_smem>>>();
        gemm64_kernel<false, true><<<GEMM_BLOCKS, 256>>>(p_ctx, out_proj_w + (size_t)i * 64 * 64,
                                                         out_proj_b + i * 64, p_Q, p_seqs);
        ln_kernel<<<WARP_BLOCKS, 256>>>(p_seqs, p_seqs, fwd_ln_g + i * 64, fwd_ln_b + i * 64);
        gemm64_kernel<true, false><<<GEMM_BLOCKS, 256>>>(p_seqs, conv1_w + (size_t)i * 64 * 64,
                                                         conv1_b + i * 64, nullptr, p_h);
        gemm64_kernel<false, true><<<GEMM_BLOCKS, 256>>>(p_h, conv2_w + (size_t)i * 64 * 64,
                                                         conv2_b + i * 64, p_seqs, p_seqs);
    }

    ln_kernel<<<WARP_BLOCKS, 256>>>(p_seqs, p_seqs, last_ln_g, last_ln_b);
    final_kernel<<<WARP_BLOCKS, 256>>>(pos_seqs, neg_seqs, item_emb, A, Bm, out);
}